// round 1
// baseline (speedup 1.0000x reference)
#include <cuda_runtime.h>
#include <math_constants.h>

// Scratch for inter-kernel z (512 x 16). Overwritten fully every launch.
__device__ float g_z[512 * 16];

// ---------------------------------------------------------------------------
// Stage 1: per (b,p) pair:
//   - compute 450 signs  s = sign(x·S1 - T1 - 1e-4)   (30 c x 15 k)
//   - for each of 10 groups g (45 signs each): scores_k = sum_j s_j * H1[j,k],
//     argmax over k=0..4095 (first occurrence), gather LUT1[g][idx][0:2]
//   - z[b, p*2 + {0,1}] = sum over g of LUT1 pairs
// Grid: 4096 blocks (b = blk>>3, p = blk&7), 256 threads.
// ---------------------------------------------------------------------------
__global__ __launch_bounds__(256, 2)
void stage1_kernel(const float* __restrict__ x,
                   const float* __restrict__ S1,
                   const float* __restrict__ H1,
                   const float* __restrict__ T1,
                   const float* __restrict__ LUT1)
{
    __shared__ float s_sm[456];        // 450 signs (padded)
    __shared__ float rmax[10][8];      // per-group per-warp max
    __shared__ int   ridx[10][8];      // per-group per-warp argmax (k index)
    __shared__ int   fidx[10];         // final per-group argmax

    const int bp  = blockIdx.x;
    const int b   = bp >> 3;
    const int p   = bp & 7;
    const int tid = threadIdx.x;

    // ---- signs ----
    const float* xr = x + b * 480 + p * 60;
    for (int f = tid; f < 450; f += 256) {
        const int c = f / 15;
        const int k = f - c * 15;
        const float x0 = xr[c * 2 + 0];
        const float x1 = xr[c * 2 + 1];
        float v = x0 * S1[(c * 2 + 0) * 15 + k];
        v = fmaf(x1, S1[(c * 2 + 1) * 15 + k], v);
        v = v - T1[c * 15 + k];
        v = v - 1e-4f;
        s_sm[f] = (v > 0.0f) ? 1.0f : ((v < 0.0f) ? -1.0f : 0.0f);
    }
    __syncthreads();

    // ---- main scores + per-thread argmax ----
    float bmax[10];
    int   bidx[10];
#pragma unroll
    for (int g = 0; g < 10; g++) { bmax[g] = -CUDART_INF_F; bidx[g] = 0; }

#pragma unroll 1
    for (int chunk = 0; chunk < 4; chunk++) {
        const int k0 = chunk * 1024 + tid * 4;
        float acc[10][4];
#pragma unroll
        for (int g = 0; g < 10; g++) {
            acc[g][0] = 0.0f; acc[g][1] = 0.0f; acc[g][2] = 0.0f; acc[g][3] = 0.0f;
        }

        const float* h1p = H1 + k0;
#pragma unroll 3
        for (int j = 0; j < 45; j++) {
            const float4 hv = *reinterpret_cast<const float4*>(h1p + j * 4096);
#pragma unroll
            for (int g = 0; g < 10; g++) {
                const float s = s_sm[g * 45 + j];
                acc[g][0] = fmaf(s, hv.x, acc[g][0]);
                acc[g][1] = fmaf(s, hv.y, acc[g][1]);
                acc[g][2] = fmaf(s, hv.z, acc[g][2]);
                acc[g][3] = fmaf(s, hv.w, acc[g][3]);
            }
        }

        // k ascending within thread (chunks ascending, q ascending); strict >
        // keeps the first occurrence, matching jnp.argmax.
#pragma unroll
        for (int g = 0; g < 10; g++) {
#pragma unroll
            for (int q = 0; q < 4; q++) {
                if (acc[g][q] > bmax[g]) { bmax[g] = acc[g][q]; bidx[g] = k0 + q; }
            }
        }
    }

    // ---- warp argmax reduce (value desc, index asc on ties) ----
#pragma unroll
    for (int g = 0; g < 10; g++) {
#pragma unroll
        for (int off = 16; off > 0; off >>= 1) {
            const float ov = __shfl_down_sync(0xffffffffu, bmax[g], off);
            const int   oi = __shfl_down_sync(0xffffffffu, bidx[g], off);
            if (ov > bmax[g] || (ov == bmax[g] && oi < bidx[g])) {
                bmax[g] = ov; bidx[g] = oi;
            }
        }
    }
    const int wid = tid >> 5;
    if ((tid & 31) == 0) {
#pragma unroll
        for (int g = 0; g < 10; g++) { rmax[g][wid] = bmax[g]; ridx[g][wid] = bidx[g]; }
    }
    __syncthreads();

    // ---- cross-warp reduce: 10 threads, one group each ----
    if (tid < 10) {
        float bv = rmax[tid][0];
        int   bi = ridx[tid][0];
#pragma unroll
        for (int w = 1; w < 8; w++) {
            const float ov = rmax[tid][w];
            const int   oi = ridx[tid][w];
            if (ov > bv || (ov == bv && oi < bi)) { bv = ov; bi = oi; }
        }
        fidx[tid] = bi;
    }
    __syncthreads();

    // ---- LUT1 gather + z accumulation (single thread, deterministic order) ----
    if (tid == 0) {
        float z0 = 0.0f, z1 = 0.0f;
#pragma unroll
        for (int g = 0; g < 10; g++) {
            const int idx = fidx[g];
            z0 += LUT1[(g * 4096 + idx) * 2 + 0];
            z1 += LUT1[(g * 4096 + idx) * 2 + 1];
        }
        g_z[b * 16 + p * 2 + 0] = z0;
        g_z[b * 16 + p * 2 + 1] = z1;
    }
}

// ---------------------------------------------------------------------------
// Stage 2: per batch row:
//   w = sign(z·S2 - T2) (0 -> -1), scores16 = w·H2, argmax over 16,
//   logits = sum_c LUT2[c][idx2_c][:], out = log_softmax(logits)
// Grid: 512 blocks, 128 threads.
// ---------------------------------------------------------------------------
__global__ __launch_bounds__(128, 8)
void stage2_kernel(const float* __restrict__ S2,
                   const float* __restrict__ H2,
                   const float* __restrict__ T2,
                   const float* __restrict__ LUT2,
                   float* __restrict__ out)
{
    __shared__ float z[16];
    __shared__ int   sidx[8];
    __shared__ float logits[100];
    __shared__ float s_lse;

    const int b   = blockIdx.x;
    const int tid = threadIdx.x;

    if (tid < 16) z[tid] = g_z[b * 16 + tid];
    __syncthreads();

    if (tid < 8) {
        const int c = tid;
        float w[15];
#pragma unroll
        for (int k = 0; k < 15; k++) {
            float v = z[2 * c + 0] * S2[(c * 2 + 0) * 15 + k];
            v = fmaf(z[2 * c + 1], S2[(c * 2 + 1) * 15 + k], v);
            v = v - T2[c * 15 + k];
            // where(v==0, -1, sign(v)) == (v > 0 ? 1 : -1)
            w[k] = (v > 0.0f) ? 1.0f : -1.0f;
        }
        float bm = -CUDART_INF_F;
        int   bi = 0;
#pragma unroll
        for (int m = 0; m < 16; m++) {
            float sc = 0.0f;
#pragma unroll
            for (int k = 0; k < 15; k++) sc = fmaf(w[k], H2[k * 16 + m], sc);
            if (sc > bm) { bm = sc; bi = m; }
        }
        sidx[c] = bi;
    }
    __syncthreads();

    if (tid < 100) {
        float l = 0.0f;
#pragma unroll
        for (int c = 0; c < 8; c++) l += LUT2[(c * 16 + sidx[c]) * 100 + tid];
        logits[tid] = l;
    }
    __syncthreads();

    if (tid == 0) {
        float mx = logits[0];
        for (int m = 1; m < 100; m++) mx = fmaxf(mx, logits[m]);
        float s = 0.0f;
        for (int m = 0; m < 100; m++) s += expf(logits[m] - mx);
        s_lse = mx + logf(s);
    }
    __syncthreads();

    if (tid < 100) out[b * 100 + tid] = logits[tid] - s_lse;
}

// ---------------------------------------------------------------------------
extern "C" void kernel_launch(void* const* d_in, const int* in_sizes, int n_in,
                              void* d_out, int out_size)
{
    const float* x    = (const float*)d_in[0];
    const float* S1   = (const float*)d_in[1];
    const float* H1   = (const float*)d_in[2];
    const float* T1   = (const float*)d_in[3];
    const float* LUT1 = (const float*)d_in[4];
    const float* S2   = (const float*)d_in[5];
    const float* H2   = (const float*)d_in[6];
    const float* T2   = (const float*)d_in[7];
    const float* LUT2 = (const float*)d_in[8];
    float* out = (float*)d_out;

    stage1_kernel<<<4096, 256>>>(x, S1, H1, T1, LUT1);
    stage2_kernel<<<512, 128>>>(S2, H2, T2, LUT2, out);
}